// round 1
// baseline (speedup 1.0000x reference)
#include <cuda_runtime.h>
#include <cuda_fp16.h>
#include <stdint.h>

// ---------------------------------------------------------------------------
// TT-linear, fully fused per-batch-element kernel.
//   y[b, o0*256+o1*16+o2] = sum_{i0,i1,i2,r1,r2}
//       core0[0,o0,i0,r1]*core1[r1,o1,i1,r2]*core2[r2,o2,i2,0]*x[b,i0*256+i1*16+i2]
//       + bias
// Three fused mma.sync GEMM stages with smem mode-permutations between them.
// ---------------------------------------------------------------------------

#define TSTR 136   // padded smem stride (halves) for 128-col tiles (conflict-free)
#define XSTR 18    // padded smem stride (halves) for 16-col tiles

// smem layout (halves):
//  Xh   : 256*XSTR   = 4608
//  M2s  : 128*XSTR   = 2304
//  M1s  : 128*TSTR   = 17408
//  M0s  : 16*TSTR    = 2176
//  T2s  : 256*TSTR   = 34816   (aliased as float Ysm[4096] in stage C)
//  T1s  : 256*TSTR   = 34816
#define OFF_XH  0
#define OFF_M2  (OFF_XH + 256*XSTR)
#define OFF_M1  (OFF_M2 + 128*XSTR)
#define OFF_M0  (OFF_M1 + 128*TSTR)
#define OFF_T2  (OFF_M0 + 16*TSTR)
#define OFF_T1  (OFF_T2 + 256*TSTR)
#define SMEM_HALVES (OFF_T1 + 256*TSTR)
#define SMEM_BYTES (SMEM_HALVES * 2)

// fp16 core matrices, pre-permuted:
//  g_M2[n=(o2*8+r2)][k=i2]        (128 x 16)
//  g_M1[n=(o1*8+r1)][k=(i1*8+r2)] (128 x 128)
//  g_M0[n=o0][k=(i0*8+r1)]        (16 x 128)
__device__ __half g_M2[128 * 16];
__device__ __half g_M1[128 * 128];
__device__ __half g_M0[16 * 128];

__global__ void tt_prep_cores(const float* __restrict__ c0,
                              const float* __restrict__ c1,
                              const float* __restrict__ c2) {
    int t = blockIdx.x * blockDim.x + threadIdx.x;
    if (t < 128 * 16) {
        int n = t >> 4, k = t & 15;           // n=(o2,r2), k=i2
        int o2 = n >> 3, r2 = n & 7;
        // core2 shape (r2=8, o2=16, i2=16, 1)
        g_M2[t] = __float2half(c2[(r2 * 16 + o2) * 16 + k]);
    }
    if (t < 128 * 128) {
        int n = t >> 7, k = t & 127;          // n=(o1,r1), k=(i1,r2)
        int o1 = n >> 3, r1 = n & 7;
        int i1 = k >> 3, r2 = k & 7;
        // core1 shape (r1=8, o1=16, i1=16, r2=8)
        g_M1[t] = __float2half(c1[((r1 * 16 + o1) * 16 + i1) * 8 + r2]);
    }
    if (t < 16 * 128) {
        int n = t >> 7, k = t & 127;          // n=o0, k=(i0,r1)
        int i0 = k >> 3, r1 = k & 7;
        // core0 shape (1, o0=16, i0=16, r1=8)
        g_M0[t] = __float2half(c0[(n * 16 + i0) * 8 + r1]);
    }
}

__device__ __forceinline__ void mma_16816(float c[4], const uint32_t a[4],
                                          const uint32_t b[2]) {
    asm volatile(
        "mma.sync.aligned.m16n8k16.row.col.f32.f16.f16.f32 "
        "{%0,%1,%2,%3}, {%4,%5,%6,%7}, {%8,%9}, {%0,%1,%2,%3};\n"
        : "+f"(c[0]), "+f"(c[1]), "+f"(c[2]), "+f"(c[3])
        : "r"(a[0]), "r"(a[1]), "r"(a[2]), "r"(a[3]), "r"(b[0]), "r"(b[1]));
}

__global__ void __launch_bounds__(512, 1)
tt_linear_kernel(const float* __restrict__ x, const float* __restrict__ bias,
                 float* __restrict__ y) {
    extern __shared__ __half smem[];
    __half* Xh  = smem + OFF_XH;
    __half* M2s = smem + OFF_M2;
    __half* M1s = smem + OFF_M1;
    __half* M0s = smem + OFF_M0;
    __half* T2s = smem + OFF_T2;
    __half* T1s = smem + OFF_T1;
    float*  Ysm = (float*)(smem + OFF_T2);   // alias: T2s dead after stage B

    const int b    = blockIdx.x;
    const int tid  = threadIdx.x;
    const int warp = tid >> 5;
    const int lane = tid & 31;
    const int g = lane >> 2;      // fragment row group 0..7
    const int c = lane & 3;       // fragment col group 0..3

    // ---- load x row (fp32 -> fp16) and core matrices into smem ----
    const float* xr = x + (size_t)b * 4096;
    for (int i = tid; i < 4096; i += 512)
        Xh[(i >> 4) * XSTR + (i & 15)] = __float2half(xr[i]);
    for (int i = tid; i < 128 * 16; i += 512)
        M2s[(i >> 4) * XSTR + (i & 15)] = g_M2[i];
    for (int i = tid; i < 128 * 128; i += 512)
        M1s[(i >> 7) * TSTR + (i & 127)] = g_M1[i];
    for (int i = tid; i < 16 * 128; i += 512)
        M0s[(i >> 7) * TSTR + (i & 127)] = g_M0[i];
    __syncthreads();

    // =======================================================================
    // Stage A: T2raw[(i0,i1) 256][(o2,r2) 128] = Xh(256x16) @ M2^T, K=16
    // scattered into T2s[(i0*16+o2)][(i1*8+r2)]
    // warp grid: 8(M) x 2(N); warp tile 32x64
    // =======================================================================
    {
        const int mw = warp >> 1, nw = warp & 1;
        float acc[2][8][4];
        #pragma unroll
        for (int mt = 0; mt < 2; mt++)
            #pragma unroll
            for (int nt = 0; nt < 8; nt++)
                #pragma unroll
                for (int q = 0; q < 4; q++) acc[mt][nt][q] = 0.f;

        uint32_t a[2][4];
        #pragma unroll
        for (int mt = 0; mt < 2; mt++) {
            const __half* base = Xh + (32 * mw + 16 * mt + g) * XSTR + 2 * c;
            a[mt][0] = *(const uint32_t*)(base);
            a[mt][1] = *(const uint32_t*)(base + 8 * XSTR);
            a[mt][2] = *(const uint32_t*)(base + 8);
            a[mt][3] = *(const uint32_t*)(base + 8 * XSTR + 8);
        }
        #pragma unroll
        for (int nt = 0; nt < 8; nt++) {
            const __half* bb = M2s + (64 * nw + 8 * nt + g) * XSTR + 2 * c;
            uint32_t brg[2];
            brg[0] = *(const uint32_t*)(bb);
            brg[1] = *(const uint32_t*)(bb + 8);
            mma_16816(acc[0][nt], a[0], brg);
            mma_16816(acc[1][nt], a[1], brg);
        }
        // scatter: (row=(i0,i1), col=(o2,r2)) -> T2s[i0*16+o2][i1*8+r2]
        #pragma unroll
        for (int mt = 0; mt < 2; mt++) {
            const int row0 = 32 * mw + 16 * mt + g;       // i1 in [0,7]
            const int i0 = row0 >> 4;
            #pragma unroll
            for (int nt = 0; nt < 8; nt++) {
                const int col0 = 64 * nw + 8 * nt + 2 * c;
                const int o2 = col0 >> 3, r2 = col0 & 7;  // r2 even
                *(half2*)&T2s[(i0 * 16 + o2) * TSTR + (row0 & 15) * 8 + r2] =
                    __floats2half2_rn(acc[mt][nt][0], acc[mt][nt][1]);
                *(half2*)&T2s[(i0 * 16 + o2) * TSTR + ((row0 + 8) & 15) * 8 + r2] =
                    __floats2half2_rn(acc[mt][nt][2], acc[mt][nt][3]);
            }
        }
    }
    __syncthreads();

    // =======================================================================
    // Stage B: T1raw[(i0,o2) 256][(o1,r1) 128] = T2s(256x128) @ M1^T, K=128
    // scattered into T1s[(o1*16+o2)][(i0*8+r1)]
    // =======================================================================
    {
        const int mw = warp >> 1, nw = warp & 1;
        float acc[2][8][4];
        #pragma unroll
        for (int mt = 0; mt < 2; mt++)
            #pragma unroll
            for (int nt = 0; nt < 8; nt++)
                #pragma unroll
                for (int q = 0; q < 4; q++) acc[mt][nt][q] = 0.f;

        #pragma unroll
        for (int kk = 0; kk < 8; kk++) {
            uint32_t a[2][4];
            #pragma unroll
            for (int mt = 0; mt < 2; mt++) {
                const __half* base =
                    T2s + (32 * mw + 16 * mt + g) * TSTR + 16 * kk + 2 * c;
                a[mt][0] = *(const uint32_t*)(base);
                a[mt][1] = *(const uint32_t*)(base + 8 * TSTR);
                a[mt][2] = *(const uint32_t*)(base + 8);
                a[mt][3] = *(const uint32_t*)(base + 8 * TSTR + 8);
            }
            #pragma unroll
            for (int nt = 0; nt < 8; nt++) {
                const __half* bb =
                    M1s + (64 * nw + 8 * nt + g) * TSTR + 16 * kk + 2 * c;
                uint32_t brg[2];
                brg[0] = *(const uint32_t*)(bb);
                brg[1] = *(const uint32_t*)(bb + 8);
                mma_16816(acc[0][nt], a[0], brg);
                mma_16816(acc[1][nt], a[1], brg);
            }
        }
        // scatter: (row=(i0,o2), col=(o1,r1)) -> T1s[o1*16+o2][i0*8+r1]
        #pragma unroll
        for (int mt = 0; mt < 2; mt++) {
            const int row0 = 32 * mw + 16 * mt + g;
            const int i0 = row0 >> 4;
            #pragma unroll
            for (int nt = 0; nt < 8; nt++) {
                const int col0 = 64 * nw + 8 * nt + 2 * c;
                const int o1 = col0 >> 3, r1 = col0 & 7;  // r1 even
                *(half2*)&T1s[(o1 * 16 + (row0 & 15)) * TSTR + i0 * 8 + r1] =
                    __floats2half2_rn(acc[mt][nt][0], acc[mt][nt][1]);
                *(half2*)&T1s[(o1 * 16 + ((row0 + 8) & 15)) * TSTR + i0 * 8 + r1] =
                    __floats2half2_rn(acc[mt][nt][2], acc[mt][nt][3]);
            }
        }
    }
    __syncthreads();

    // =======================================================================
    // Stage C: Y[(o1,o2) 256][o0 16] = T1s(256x128) @ M0^T, K=128
    // y index = b*4096 + o0*256 + (o1*16+o2)  -> Ysm[col*256+row], then
    // coalesced global store with bias.
    // =======================================================================
    {
        float acc[2][4];
        #pragma unroll
        for (int nt = 0; nt < 2; nt++)
            #pragma unroll
            for (int q = 0; q < 4; q++) acc[nt][q] = 0.f;

        #pragma unroll
        for (int kk = 0; kk < 8; kk++) {
            uint32_t a[4];
            const __half* base = T1s + (16 * warp + g) * TSTR + 16 * kk + 2 * c;
            a[0] = *(const uint32_t*)(base);
            a[1] = *(const uint32_t*)(base + 8 * TSTR);
            a[2] = *(const uint32_t*)(base + 8);
            a[3] = *(const uint32_t*)(base + 8 * TSTR + 8);
            #pragma unroll
            for (int nt = 0; nt < 2; nt++) {
                const __half* bb = M0s + (8 * nt + g) * TSTR + 16 * kk + 2 * c;
                uint32_t brg[2];
                brg[0] = *(const uint32_t*)(bb);
                brg[1] = *(const uint32_t*)(bb + 8);
                mma_16816(acc[nt], a, brg);
            }
        }
        // Ysm aliases T2s (dead after stage B; sync above guarantees ordering)
        #pragma unroll
        for (int nt = 0; nt < 2; nt++) {
            const int row0 = 16 * warp + g;
            const int col0 = 8 * nt + 2 * c;
            Ysm[(col0)     * 256 + row0]     = acc[nt][0];
            Ysm[(col0 + 1) * 256 + row0]     = acc[nt][1];
            Ysm[(col0)     * 256 + row0 + 8] = acc[nt][2];
            Ysm[(col0 + 1) * 256 + row0 + 8] = acc[nt][3];
        }
    }
    __syncthreads();

    float* yr = y + (size_t)b * 4096;
    for (int i = tid; i < 4096; i += 512)
        yr[i] = Ysm[i] + bias[i];
}

extern "C" void kernel_launch(void* const* d_in, const int* in_sizes, int n_in,
                              void* d_out, int out_size) {
    const float* x    = (const float*)d_in[0];
    const float* c0   = (const float*)d_in[1];
    const float* c1   = (const float*)d_in[2];
    const float* c2   = (const float*)d_in[3];
    const float* bias = (const float*)d_in[4];
    float* y = (float*)d_out;

    cudaFuncSetAttribute(tt_linear_kernel,
                         cudaFuncAttributeMaxDynamicSharedMemorySize,
                         SMEM_BYTES);

    tt_prep_cores<<<32, 512>>>(c0, c1, c2);
    tt_linear_kernel<<<8192, 512, SMEM_BYTES>>>(x, bias, y);
}

// round 3
// speedup vs baseline: 2.2761x; 2.2761x over previous
#include <cuda_runtime.h>
#include <cuda_fp16.h>
#include <stdint.h>

// ---------------------------------------------------------------------------
// TT-linear fused kernel, v3 (v2 with corrected ldmatrix B-operand usage).
// One batch row per CTA (256 threads, 8 warps), i0 chunked 8-at-a-time
// (2 chunks). Three mma.sync stages, non-trans LDSM for both A and B
// fragments ([n][k] row-major B storage), stage-C accumulators in registers.
// 110KB smem -> 2 CTAs/SM.
// ---------------------------------------------------------------------------

#define M1STR 136
#define M0STR 136
#define T2STR 136
#define T1STR 72

#define OFF_M1 0
#define OFF_M0 (OFF_M1 + 128 * M1STR)   // 17408
#define OFF_T2 (OFF_M0 + 16 * M0STR)    // 19584
#define OFF_T1 (OFF_T2 + 128 * T2STR)   // 36992
#define SMEM_HALVES (OFF_T1 + 256 * T1STR)  // 55424
#define SMEM_BYTES (SMEM_HALVES * 2)        // 110848

// fp16 core matrices, pre-permuted:
//  g_M2[n=(o2*8+r2)][k=i2]        (128 x 16)
//  g_M1[n=(o1*8+r1)][k=(i1*8+r2)] (128 x 128)
//  g_M0[n=o0][k=(i0*8+r1)]        (16 x 128)
__device__ __half g_M2[128 * 16];
__device__ __half g_M1[128 * 128];
__device__ __half g_M0[16 * 128];

__global__ void tt_prep_cores(const float* __restrict__ c0,
                              const float* __restrict__ c1,
                              const float* __restrict__ c2) {
    int t = blockIdx.x * blockDim.x + threadIdx.x;
    if (t < 128 * 16) {
        int n = t >> 4, k = t & 15;
        int o2 = n >> 3, r2 = n & 7;
        g_M2[t] = __float2half(c2[(r2 * 16 + o2) * 16 + k]);
    }
    if (t < 128 * 128) {
        int n = t >> 7, k = t & 127;
        int o1 = n >> 3, r1 = n & 7;
        int i1 = k >> 3, r2 = k & 7;
        g_M1[t] = __float2half(c1[((r1 * 16 + o1) * 16 + i1) * 8 + r2]);
    }
    if (t < 16 * 128) {
        int n = t >> 7, k = t & 127;
        int i0 = k >> 3, r1 = k & 7;
        g_M0[t] = __float2half(c0[(n * 16 + i0) * 8 + r1]);
    }
}

__device__ __forceinline__ void mma16816(float* d, const uint32_t* a,
                                         uint32_t b0, uint32_t b1) {
    asm volatile(
        "mma.sync.aligned.m16n8k16.row.col.f32.f16.f16.f32 "
        "{%0,%1,%2,%3}, {%4,%5,%6,%7}, {%8,%9}, {%0,%1,%2,%3};\n"
        : "+f"(d[0]), "+f"(d[1]), "+f"(d[2]), "+f"(d[3])
        : "r"(a[0]), "r"(a[1]), "r"(a[2]), "r"(a[3]), "r"(b0), "r"(b1));
}

__device__ __forceinline__ void ldsm4(uint32_t* r, uint32_t addr) {
    asm volatile(
        "ldmatrix.sync.aligned.m8n8.x4.shared.b16 {%0,%1,%2,%3}, [%4];\n"
        : "=r"(r[0]), "=r"(r[1]), "=r"(r[2]), "=r"(r[3]) : "r"(addr));
}

__device__ __forceinline__ uint32_t packh2(float lo, float hi) {
    __half2 h = __floats2half2_rn(lo, hi);
    return *(uint32_t*)&h;
}

__global__ void __launch_bounds__(256, 2)
tt_linear_kernel(const float* __restrict__ x, const float* __restrict__ bias,
                 float* __restrict__ y) {
    extern __shared__ __half smem[];
    __half* M1s = smem + OFF_M1;
    __half* M0s = smem + OFF_M0;
    __half* T2c = smem + OFF_T2;   // 128 rows (li0*16+o2) x 128 (i1*8+r2)
    __half* T1c = smem + OFF_T1;   // 256 rows (o1*16+o2) x 64 (li0*8+r1)

    const int b    = blockIdx.x;
    const int tid  = threadIdx.x;
    const int w    = tid >> 5;
    const int lane = tid & 31;
    const int g = lane >> 2, c = lane & 3;
    const int lsel = lane & 15;            // LDSM row select
    const int lhi8 = (lane >> 4) << 3;     // LDSM k offset (0/8)

    const uint32_t sT2 = (uint32_t)__cvta_generic_to_shared(T2c);
    const uint32_t sT1 = (uint32_t)__cvta_generic_to_shared(T1c);
    const uint32_t sM1 = (uint32_t)__cvta_generic_to_shared(M1s);
    const uint32_t sM0 = (uint32_t)__cvta_generic_to_shared(M0s);

    // ---- prologue: copy M1, M0 into smem (16B vectors) ----
    {
        const uint4* s1 = (const uint4*)g_M1;   // 2048 uint4
        #pragma unroll
        for (int i = 0; i < 8; i++) {
            int idx = tid + 256 * i;
            int n = idx >> 4, ch = idx & 15;
            *(uint4*)&M1s[n * M1STR + ch * 8] = s1[idx];
        }
        const uint4* s0 = (const uint4*)g_M0;   // 256 uint4
        int n = tid >> 4, ch = tid & 15;
        *(uint4*)&M0s[n * M0STR + ch * 8] = s0[tid];
    }

    const float* xr = x + (size_t)b * 4096;

    float accc[2][2][4];
    #pragma unroll
    for (int mi = 0; mi < 2; mi++)
        #pragma unroll
        for (int nt = 0; nt < 2; nt++)
            #pragma unroll
            for (int q = 0; q < 4; q++) accc[mi][nt][q] = 0.f;

    // ---- stage A: X(rows i0 in chunk t) @ M2^T -> scatter to T2c ----
    auto stageA = [&](int t) {
        uint32_t a[2][4];
        #pragma unroll
        for (int mi = 0; mi < 2; mi++) {
            const int mt = (w & 3) + 4 * mi;          // local i0
            const float* rp = xr + (8 * t + mt) * 256 + 16 * g + 2 * c;
            float2 f;
            f = *(const float2*)(rp);        a[mi][0] = packh2(f.x, f.y);
            f = *(const float2*)(rp + 128);  a[mi][1] = packh2(f.x, f.y);
            f = *(const float2*)(rp + 8);    a[mi][2] = packh2(f.x, f.y);
            f = *(const float2*)(rp + 136);  a[mi][3] = packh2(f.x, f.y);
        }
        #pragma unroll
        for (int j = 0; j < 8; j++) {
            const int nt = 8 * (w >> 2) + j;          // o2
            // B fragment direct from gmem [n][k] storage: {B(k=2c,n=g),...}
            uint32_t b0 = *(const uint32_t*)&g_M2[(8 * nt + g) * 16 + 2 * c];
            uint32_t b1 = *(const uint32_t*)&g_M2[(8 * nt + g) * 16 + 2 * c + 8];
            #pragma unroll
            for (int mi = 0; mi < 2; mi++) {
                const int mt = (w & 3) + 4 * mi;
                float d[4] = {0.f, 0.f, 0.f, 0.f};
                mma16816(d, a[mi], b0, b1);
                // rows = i1 (g, g+8); cols (o2=nt, r2=2c,2c+1)
                __half* p = &T2c[(16 * mt + nt) * T2STR + 8 * g + 2 * c];
                *(half2*)p        = __floats2half2_rn(d[0], d[1]);
                *(half2*)(p + 64) = __floats2half2_rn(d[2], d[3]);
            }
        }
    };

    // ---- stage B: T2c @ M1^T -> scatter to T1c ----
    auto stageB = [&]() {
        float accb[2][8][4];
        #pragma unroll
        for (int mi = 0; mi < 2; mi++)
            #pragma unroll
            for (int j = 0; j < 8; j++)
                #pragma unroll
                for (int q = 0; q < 4; q++) accb[mi][j][q] = 0.f;

        #pragma unroll
        for (int kk = 0; kk < 8; kk++) {
            uint32_t a[2][4];
            #pragma unroll
            for (int mi = 0; mi < 2; mi++) {
                const int mt = (w & 3) + 4 * mi;      // local i0
                ldsm4(a[mi], sT2 + ((16 * mt + lsel) * T2STR + 16 * kk + lhi8) * 2);
            }
            #pragma unroll
            for (int jp = 0; jp < 4; jp++) {
                // n block of 16: rows n0..n0+15 of M1s
                const int n0 = 64 * (w >> 2) + 16 * jp;
                uint32_t bb[4];
                ldsm4(bb, sM1 + ((n0 + lsel) * M1STR + 16 * kk + lhi8) * 2);
                // pairs: {bb[0],bb[2]} = n0..n0+7, {bb[1],bb[3]} = n0+8..n0+15
                mma16816(accb[0][2 * jp],     a[0], bb[0], bb[2]);
                mma16816(accb[0][2 * jp + 1], a[0], bb[1], bb[3]);
                mma16816(accb[1][2 * jp],     a[1], bb[0], bb[2]);
                mma16816(accb[1][2 * jp + 1], a[1], bb[1], bb[3]);
            }
        }
        // scatter: rows=(li0=mt, o2=g/g+8), cols (o1=nt, r1=2c,2c+1)
        #pragma unroll
        for (int mi = 0; mi < 2; mi++) {
            const int mt = (w & 3) + 4 * mi;
            #pragma unroll
            for (int j = 0; j < 8; j++) {
                const int nt = 8 * (w >> 2) + j;
                __half* p = &T1c[(16 * nt + g) * T1STR + 8 * mt + 2 * c];
                *(half2*)p               = __floats2half2_rn(accb[mi][j][0], accb[mi][j][1]);
                *(half2*)(p + 8 * T1STR) = __floats2half2_rn(accb[mi][j][2], accb[mi][j][3]);
            }
        }
    };

    // ---- stage C: T1c @ M0^T (K=64 this chunk) -> register accumulators ----
    auto stageC = [&](int t) {
        #pragma unroll
        for (int ks = 0; ks < 4; ks++) {
            uint32_t a[2][4];
            #pragma unroll
            for (int mi = 0; mi < 2; mi++) {
                const int m = w + 8 * mi;
                ldsm4(a[mi], sT1 + ((16 * m + lsel) * T1STR + 16 * ks + lhi8) * 2);
            }
            uint32_t bb[4];
            ldsm4(bb, sM0 + (lsel * M0STR + 64 * t + 16 * ks + lhi8) * 2);
            mma16816(accc[0][0], a[0], bb[0], bb[2]);
            mma16816(accc[0][1], a[0], bb[1], bb[3]);
            mma16816(accc[1][0], a[1], bb[0], bb[2]);
            mma16816(accc[1][1], a[1], bb[1], bb[3]);
        }
    };

    // ---- pipeline ----
    stageA(0);
    __syncthreads();
    stageB();
    __syncthreads();
    stageC(0);
    stageA(1);
    __syncthreads();
    stageB();
    __syncthreads();
    stageC(1);

    // ---- epilogue: y[b, o0*256 + o1*16 + o2] = accc + bias ----
    float* yr = y + (size_t)b * 4096;
    #pragma unroll
    for (int mi = 0; mi < 2; mi++) {
        const int row0 = 16 * (w + 8 * mi) + g;       // o1*16+o2
        #pragma unroll
        for (int nt = 0; nt < 2; nt++) {
            const int col0 = 8 * nt + 2 * c;          // o0
            const int i00 = col0 * 256 + row0;
            yr[i00]       = accc[mi][nt][0] + __ldg(&bias[i00]);
            yr[i00 + 256] = accc[mi][nt][1] + __ldg(&bias[i00 + 256]);
            yr[i00 + 8]   = accc[mi][nt][2] + __ldg(&bias[i00 + 8]);
            yr[i00 + 264] = accc[mi][nt][3] + __ldg(&bias[i00 + 264]);
        }
    }
}

extern "C" void kernel_launch(void* const* d_in, const int* in_sizes, int n_in,
                              void* d_out, int out_size) {
    const float* x    = (const float*)d_in[0];
    const float* c0   = (const float*)d_in[1];
    const float* c1   = (const float*)d_in[2];
    const float* c2   = (const float*)d_in[3];
    const float* bias = (const float*)d_in[4];
    float* y = (float*)d_out;

    cudaFuncSetAttribute(tt_linear_kernel,
                         cudaFuncAttributeMaxDynamicSharedMemorySize,
                         SMEM_BYTES);

    tt_prep_cores<<<32, 512>>>(c0, c1, c2);
    tt_linear_kernel<<<8192, 256, SMEM_BYTES>>>(x, bias, y);
}

// round 5
// speedup vs baseline: 2.3427x; 1.0292x over previous
#include <cuda_runtime.h>
#include <cuda_fp16.h>
#include <stdint.h>

// ---------------------------------------------------------------------------
// TT-linear fused kernel, v5 (R3 + coalesced transposed epilogue + float4
// stage-A x loads via K-permuted M2). All mma.sync; tcgen05 unavailable
// (harness compiles via compute_103 virtual arch, no 'a' features).
// ---------------------------------------------------------------------------

#define M1STR 136
#define M0STR 136
#define T2STR 136
#define T1STR 72
#define YSTR  260

#define OFF_M1 0
#define OFF_M0 (OFF_M1 + 128 * M1STR)   // 17408
#define OFF_T2 (OFF_M0 + 16 * M0STR)    // 19584
#define OFF_T1 (OFF_T2 + 128 * T2STR)   // 36992
#define SMEM_HALVES (OFF_T1 + 256 * T1STR)  // 55424
#define SMEM_BYTES (SMEM_HALVES * 2)        // 110848

// fp16 core matrices, pre-permuted:
//  g_M2[n=(o2*8+r2)][k]           (128 x 16), column k holds i2 = sigma(k)
//  g_M1[n=(o1*8+r1)][k=(i1*8+r2)] (128 x 128)
//  g_M0[n=o0][k=(i0*8+r1)]        (16 x 128)
__device__ __half g_M2[128 * 16];
__device__ __half g_M1[128 * 128];
__device__ __half g_M0[16 * 128];

__global__ void tt_prep_cores(const float* __restrict__ c0,
                              const float* __restrict__ c1,
                              const float* __restrict__ c2) {
    int t = blockIdx.x * blockDim.x + threadIdx.x;
    if (t < 128 * 16) {
        int n = t >> 4, k = t & 15;
        int o2 = n >> 3, r2 = n & 7;
        // sigma: logical mma-k -> physical i2, so a float4 at i2=4c covers
        // the lane's fragment {2c,2c+1,2c+8,2c+9}.
        int cc = (k >> 1) & 3, d = k & 1, e = k >> 3;
        int i2 = 4 * cc + 2 * e + d;
        g_M2[t] = __float2half(c2[(r2 * 16 + o2) * 16 + i2]);
    }
    if (t < 128 * 128) {
        int n = t >> 7, k = t & 127;
        int o1 = n >> 3, r1 = n & 7;
        int i1 = k >> 3, r2 = k & 7;
        g_M1[t] = __float2half(c1[((r1 * 16 + o1) * 16 + i1) * 8 + r2]);
    }
    if (t < 16 * 128) {
        int n = t >> 7, k = t & 127;
        int i0 = k >> 3, r1 = k & 7;
        g_M0[t] = __float2half(c0[(n * 16 + i0) * 8 + r1]);
    }
}

__device__ __forceinline__ void mma16816(float* d, const uint32_t* a,
                                         uint32_t b0, uint32_t b1) {
    asm volatile(
        "mma.sync.aligned.m16n8k16.row.col.f32.f16.f16.f32 "
        "{%0,%1,%2,%3}, {%4,%5,%6,%7}, {%8,%9}, {%0,%1,%2,%3};\n"
        : "+f"(d[0]), "+f"(d[1]), "+f"(d[2]), "+f"(d[3])
        : "r"(a[0]), "r"(a[1]), "r"(a[2]), "r"(a[3]), "r"(b0), "r"(b1));
}

__device__ __forceinline__ void ldsm4(uint32_t* r, uint32_t addr) {
    asm volatile(
        "ldmatrix.sync.aligned.m8n8.x4.shared.b16 {%0,%1,%2,%3}, [%4];\n"
        : "=r"(r[0]), "=r"(r[1]), "=r"(r[2]), "=r"(r[3]) : "r"(addr));
}

__device__ __forceinline__ uint32_t packh2(float lo, float hi) {
    __half2 h = __floats2half2_rn(lo, hi);
    return *(uint32_t*)&h;
}

__global__ void __launch_bounds__(256, 2)
tt_linear_kernel(const float* __restrict__ x, const float* __restrict__ bias,
                 float* __restrict__ y) {
    extern __shared__ __half smem[];
    __half* M1s = smem + OFF_M1;
    __half* M0s = smem + OFF_M0;
    __half* T2c = smem + OFF_T2;   // 128 rows (li0*16+o2) x 128 (i1*8+r2)
    __half* T1c = smem + OFF_T1;   // 256 rows (o1*16+o2) x 64 (li0*8+r1)
    float*  Ysm = (float*)(smem + OFF_T2);  // aliases T2 (dead after B(1))

    const int b    = blockIdx.x;
    const int tid  = threadIdx.x;
    const int w    = tid >> 5;
    const int lane = tid & 31;
    const int g = lane >> 2, c = lane & 3;
    const int lsel = lane & 15;            // LDSM row select
    const int lhi8 = (lane >> 4) << 3;     // LDSM k offset (0/8)

    const uint32_t sT2 = (uint32_t)__cvta_generic_to_shared(T2c);
    const uint32_t sT1 = (uint32_t)__cvta_generic_to_shared(T1c);
    const uint32_t sM1 = (uint32_t)__cvta_generic_to_shared(M1s);
    const uint32_t sM0 = (uint32_t)__cvta_generic_to_shared(M0s);

    // ---- prologue: copy M1, M0 into smem (16B vectors) ----
    {
        const uint4* s1 = (const uint4*)g_M1;   // 2048 uint4
        #pragma unroll
        for (int i = 0; i < 8; i++) {
            int idx = tid + 256 * i;
            int n = idx >> 4, ch = idx & 15;
            *(uint4*)&M1s[n * M1STR + ch * 8] = s1[idx];
        }
        const uint4* s0 = (const uint4*)g_M0;   // 256 uint4
        int n = tid >> 4, ch = tid & 15;
        *(uint4*)&M0s[n * M0STR + ch * 8] = s0[tid];
    }

    const float* xr = x + (size_t)b * 4096;

    float accc[2][2][4];
    #pragma unroll
    for (int mi = 0; mi < 2; mi++)
        #pragma unroll
        for (int nt = 0; nt < 2; nt++)
            #pragma unroll
            for (int q = 0; q < 4; q++) accc[mi][nt][q] = 0.f;

    // ---- stage A: X(rows i0 in chunk t) @ M2^T -> scatter to T2c ----
    auto stageA = [&](int t) {
        uint32_t a[2][4];
        #pragma unroll
        for (int mi = 0; mi < 2; mi++) {
            const int mt = (w & 3) + 4 * mi;          // local i0
            // float4 covers physical i2 = 4c..4c+3 = logical k {2c,2c+1,2c+8,2c+9}
            const float* rp = xr + (8 * t + mt) * 256 + 16 * g + 4 * c;
            float4 f0 = *(const float4*)(rp);         // A-row g
            float4 f1 = *(const float4*)(rp + 128);   // A-row g+8
            a[mi][0] = packh2(f0.x, f0.y);
            a[mi][1] = packh2(f1.x, f1.y);
            a[mi][2] = packh2(f0.z, f0.w);
            a[mi][3] = packh2(f1.z, f1.w);
        }
        #pragma unroll
        for (int j = 0; j < 8; j++) {
            const int nt = 8 * (w >> 2) + j;          // o2
            uint32_t b0 = *(const uint32_t*)&g_M2[(8 * nt + g) * 16 + 2 * c];
            uint32_t b1 = *(const uint32_t*)&g_M2[(8 * nt + g) * 16 + 2 * c + 8];
            #pragma unroll
            for (int mi = 0; mi < 2; mi++) {
                const int mt = (w & 3) + 4 * mi;
                float d[4] = {0.f, 0.f, 0.f, 0.f};
                mma16816(d, a[mi], b0, b1);
                // rows = i1 (g, g+8); cols (o2=nt, r2=2c,2c+1)
                __half* p = &T2c[(16 * mt + nt) * T2STR + 8 * g + 2 * c];
                *(half2*)p        = __floats2half2_rn(d[0], d[1]);
                *(half2*)(p + 64) = __floats2half2_rn(d[2], d[3]);
            }
        }
    };

    // ---- stage B: T2c @ M1^T -> scatter to T1c ----
    auto stageB = [&]() {
        float accb[2][8][4];
        #pragma unroll
        for (int mi = 0; mi < 2; mi++)
            #pragma unroll
            for (int j = 0; j < 8; j++)
                #pragma unroll
                for (int q = 0; q < 4; q++) accb[mi][j][q] = 0.f;

        #pragma unroll
        for (int kk = 0; kk < 8; kk++) {
            uint32_t a[2][4];
            #pragma unroll
            for (int mi = 0; mi < 2; mi++) {
                const int mt = (w & 3) + 4 * mi;      // local i0
                ldsm4(a[mi], sT2 + ((16 * mt + lsel) * T2STR + 16 * kk + lhi8) * 2);
            }
            #pragma unroll
            for (int jp = 0; jp < 4; jp++) {
                const int n0 = 64 * (w >> 2) + 16 * jp;
                uint32_t bb[4];
                ldsm4(bb, sM1 + ((n0 + lsel) * M1STR + 16 * kk + lhi8) * 2);
                mma16816(accb[0][2 * jp],     a[0], bb[0], bb[2]);
                mma16816(accb[0][2 * jp + 1], a[0], bb[1], bb[3]);
                mma16816(accb[1][2 * jp],     a[1], bb[0], bb[2]);
                mma16816(accb[1][2 * jp + 1], a[1], bb[1], bb[3]);
            }
        }
        // scatter: rows=(li0=mt, o2=g/g+8), cols (o1=nt, r1=2c,2c+1)
        #pragma unroll
        for (int mi = 0; mi < 2; mi++) {
            const int mt = (w & 3) + 4 * mi;
            #pragma unroll
            for (int j = 0; j < 8; j++) {
                const int nt = 8 * (w >> 2) + j;
                __half* p = &T1c[(16 * nt + g) * T1STR + 8 * mt + 2 * c];
                *(half2*)p               = __floats2half2_rn(accb[mi][j][0], accb[mi][j][1]);
                *(half2*)(p + 8 * T1STR) = __floats2half2_rn(accb[mi][j][2], accb[mi][j][3]);
            }
        }
    };

    // ---- stage C: T1c @ M0^T (K=64 per chunk) -> register accumulators ----
    auto stageC = [&](int t) {
        #pragma unroll
        for (int ks = 0; ks < 4; ks++) {
            uint32_t a[2][4];
            #pragma unroll
            for (int mi = 0; mi < 2; mi++) {
                const int m = w + 8 * mi;
                ldsm4(a[mi], sT1 + ((16 * m + lsel) * T1STR + 16 * ks + lhi8) * 2);
            }
            uint32_t bb[4];
            ldsm4(bb, sM0 + (lsel * M0STR + 64 * t + 16 * ks + lhi8) * 2);
            mma16816(accc[0][0], a[0], bb[0], bb[2]);
            mma16816(accc[0][1], a[0], bb[1], bb[3]);
            mma16816(accc[1][0], a[1], bb[0], bb[2]);
            mma16816(accc[1][1], a[1], bb[1], bb[3]);
        }
    };

    // ---- pipeline ----
    stageA(0);
    __syncthreads();
    stageB();
    __syncthreads();
    stageC(0);
    stageA(1);
    __syncthreads();
    stageB();
    __syncthreads();
    stageC(1);

    // ---- epilogue: transpose through Ysm, then coalesced bias+store ----
    // Ysm[o0][row=(o1*16+o2)], stride YSTR=260 (bank map 8c+g: conflict-free)
    #pragma unroll
    for (int mi = 0; mi < 2; mi++) {
        const int row0 = 16 * (w + 8 * mi) + g;       // o1*16+o2
        #pragma unroll
        for (int nt = 0; nt < 2; nt++) {
            const int col0 = 8 * nt + 2 * c;          // o0
            Ysm[(col0)     * YSTR + row0]     = accc[mi][nt][0];
            Ysm[(col0 + 1) * YSTR + row0]     = accc[mi][nt][1];
            Ysm[(col0)     * YSTR + row0 + 8] = accc[mi][nt][2];
            Ysm[(col0 + 1) * YSTR + row0 + 8] = accc[mi][nt][3];
        }
    }
    __syncthreads();

    float* yr = y + (size_t)b * 4096;
    #pragma unroll
    for (int it = 0; it < 16; it++) {
        const int i = tid + 256 * it;                 // i = o0*256 + row
        const int o0 = i >> 8, row = i & 255;
        yr[i] = Ysm[o0 * YSTR + row] + bias[i];
    }
}

extern "C" void kernel_launch(void* const* d_in, const int* in_sizes, int n_in,
                              void* d_out, int out_size) {
    const float* x    = (const float*)d_in[0];
    const float* c0   = (const float*)d_in[1];
    const float* c1   = (const float*)d_in[2];
    const float* c2   = (const float*)d_in[3];
    const float* bias = (const float*)d_in[4];
    float* y = (float*)d_out;

    cudaFuncSetAttribute(tt_linear_kernel,
                         cudaFuncAttributeMaxDynamicSharedMemorySize,
                         SMEM_BYTES);

    tt_prep_cores<<<32, 512>>>(c0, c1, c2);
    tt_linear_kernel<<<8192, 256, SMEM_BYTES>>>(x, bias, y);
}